// round 9
// baseline (speedup 1.0000x reference)
#include <cuda_runtime.h>
#include <cuda_bf16.h>
#include <math.h>
#include <stdint.h>

#define NN 100000
#define NE 1600000
#define NG 64
#define FD 50
#define KA 256        // A columns: [h(50) | mean mn mx sd (200) | pad(6)]
#define NB 192        // B columns: 3 blocks of 64
#define NL 3
#define ASTR 40       // smem row stride in bf16 (32 + 8 pad)

// ---------------- static scratch ----------------
__device__ int    g_deg[NN];
__device__ int    g_rowptr[NN + 1];
__device__ int    g_cursor[NN];
__device__ int    g_col[NE];
__device__ float  g_dinv[NN];
__device__ float  g_amp[NN];
__device__ float  g_att[NN];
__device__ double g_avg;
__device__ float  g_h[NN * FD];
__device__ float  g_h2[NN * FD];
__device__ float  g_h0s[NN * FD];
__device__ float  g_base[NN * FD];
__device__ float  g_y[NN * FD];
__device__ __align__(16) __nv_bfloat16 g_extH[(size_t)NN * KA];  // ~51MB
__device__ __align__(16) __nv_bfloat16 g_extL[(size_t)NN * KA];  // ~51MB
__device__ __align__(16) __nv_bfloat16 g_CH[NL * NB * KA];
__device__ __align__(16) __nv_bfloat16 g_CL[NL * NB * KA];
__device__ double g_bns[2 * 64];
__device__ float  g_scale[64];
__device__ float  g_shift[64];
__device__ float  g_gr[NG * FD];

// ---------------- helpers ----------------
__device__ __forceinline__ uint32_t smem_u32(const void* p) {
    uint32_t a;
    asm("{ .reg .u64 t; cvta.to.shared.u64 t, %1; cvt.u32.u64 %0, t; }" : "=r"(a) : "l"(p));
    return a;
}
__device__ __forceinline__ void ldsm4(uint32_t* r, uint32_t a) {
    asm volatile("ldmatrix.sync.aligned.m8n8.x4.shared.b16 {%0,%1,%2,%3}, [%4];"
        : "=r"(r[0]), "=r"(r[1]), "=r"(r[2]), "=r"(r[3]) : "r"(a));
}
__device__ __forceinline__ void mma_bf16(float* d, const uint32_t* a, const uint32_t* b) {
    asm volatile("mma.sync.aligned.m16n8k16.row.col.f32.bf16.bf16.f32 "
        "{%0,%1,%2,%3}, {%4,%5,%6,%7}, {%8,%9}, {%0,%1,%2,%3};"
        : "+f"(d[0]), "+f"(d[1]), "+f"(d[2]), "+f"(d[3])
        : "r"(a[0]), "r"(a[1]), "r"(a[2]), "r"(a[3]), "r"(b[0]), "r"(b[1]));
}
__device__ __forceinline__ void bsplit(float v, __nv_bfloat16* H, __nv_bfloat16* L, size_t i) {
    __nv_bfloat16 h = __float2bfloat16(v);
    H[i] = h;
    L[i] = __float2bfloat16(v - __bfloat162float(h));
}

// ---------------- setup kernels ----------------
__global__ void __launch_bounds__(256) k_zero0() {
    int i = blockIdx.x * 256 + threadIdx.x;
    if (i < NN) g_deg[i] = 0;
    if (i == 0) g_avg = 0.0;
}

__global__ void __launch_bounds__(256) k_hist(const int* __restrict__ dst) {
    int e = blockIdx.x * 256 + threadIdx.x;
    if (e < NE) atomicAdd(&g_deg[dst[e]], 1);
}

#define SCAN_T 1024
#define SCAN_CHUNK 98
__global__ void __launch_bounds__(SCAN_T) k_scan() {
    __shared__ int part[SCAN_T];
    int t = threadIdx.x;
    int st = t * SCAN_CHUNK;
    int s = 0;
    for (int i = 0; i < SCAN_CHUNK; i++) {
        int idx = st + i;
        if (idx < NN) s += g_deg[idx];
    }
    part[t] = s;
    __syncthreads();
    for (int off = 1; off < SCAN_T; off <<= 1) {
        int v = 0;
        if (t >= off) v = part[t - off];
        __syncthreads();
        part[t] += v;
        __syncthreads();
    }
    int run = part[t] - s;
    for (int i = 0; i < SCAN_CHUNK; i++) {
        int idx = st + i;
        if (idx < NN) { g_rowptr[idx] = run; run += g_deg[idx]; }
    }
    if (t == SCAN_T - 1) g_rowptr[NN] = part[SCAN_T - 1];
}

__global__ void __launch_bounds__(256) k_dinv() {
    int v = blockIdx.x * 256 + threadIdx.x;
    float lg = 0.f;
    if (v < NN) {
        int d = g_deg[v];
        g_dinv[v] = rsqrtf((float)(d + 1));
        g_cursor[v] = g_rowptr[v];
        lg = log1pf((float)d);
    }
    for (int o = 16; o; o >>= 1) lg += __shfl_down_sync(0xffffffffu, lg, o);
    __shared__ float ws[8];
    int w = threadIdx.x >> 5, ln = threadIdx.x & 31;
    if (ln == 0) ws[w] = lg;
    __syncthreads();
    if (threadIdx.x == 0) {
        float tt = 0.f;
        for (int i = 0; i < 8; i++) tt += ws[i];
        atomicAdd(&g_avg, (double)tt);
    }
}

__global__ void __launch_bounds__(256) k_scatter(const int* __restrict__ src,
                                                 const int* __restrict__ dst) {
    int e = blockIdx.x * 256 + threadIdx.x;
    if (e < NE) {
        int d = dst[e];
        int p = atomicAdd(&g_cursor[d], 1);
        g_col[p] = src[e];
    }
}

__global__ void __launch_bounds__(256) k_h0s(const float* __restrict__ x,
                                             const float* __restrict__ Wg) {
    int idx = blockIdx.x * 256 + threadIdx.x;
    if (idx < NN * FD) {
        int v = idx / FD;
        int f = idx - v * FD;
        float h0 = x[2 * v] * Wg[f] + x[2 * v + 1] * Wg[FD + f];
        g_h0s[idx] = h0 * g_dinv[v];
    }
}

__global__ void __launch_bounds__(256) k_amp() {
    int v = blockIdx.x * 256 + threadIdx.x;
    if (v < NN) {
        float avgl = (float)(g_avg / (double)NN);
        int d = g_deg[v];
        float dc = fmaxf((float)d, 1.f);
        float lg = log1pf(dc);
        g_amp[v] = lg / avgl;
        g_att[v] = avgl / lg;
    }
}

__global__ void __launch_bounds__(256) k_gcn(const float* __restrict__ bg) {
    int tid = threadIdx.x;
    int grp = tid >> 6, f = tid & 63;
    int v = blockIdx.x * 4 + grp;
    if (f >= FD) return;
    int r0 = g_rowptr[v], r1 = g_rowptr[v + 1];
    float s = 0.f;
    for (int i = r0; i < r1; i++) {
        int u = g_col[i];
        s += g_h0s[(size_t)u * FD + f];
    }
    g_h[(size_t)v * FD + f] = g_dinv[v] * (s + g_h0s[(size_t)v * FD + f]) + bg[f];
}

// ---------------- combined weights (rank-compressed) ----------------
// B[l][n2][k], n2 = blk*64 + n (n<64). Out = blk0 + amp*blk1 + att*blk2.
// k<50:  x-part -> only blk 0 (postW row k)
// 50<=k<250: agg-part -> postW row 50 + blk*200 + (k-50)
__global__ void __launch_bounds__(256) k_combW(const float* __restrict__ postW,
                                               const float* __restrict__ linW) {
    int idx = blockIdx.x * 256 + threadIdx.x;
    if (idx >= NL * NB * KA) return;
    int l = idx / (NB * KA);
    int r = idx - l * (NB * KA);
    int n2 = r / KA;
    int k = r - n2 * KA;
    int blk = n2 >> 6;
    int n = n2 & 63;
    float v = 0.f;
    int row = -1;
    if (k < FD) { if (blk == 0) row = k; }
    else if (k < 250) row = FD + blk * 200 + (k - FD);
    if (row >= 0 && n < FD) {
        const float* wq = postW + ((size_t)l * 650 + row) * FD;
        const float* wl = linW + (size_t)l * FD * FD;
        #pragma unroll 10
        for (int j = 0; j < FD; j++) v += wq[j] * wl[j * FD + n];
    }
    bsplit(v, g_CH, g_CL, idx);
}

// ---------------- per-layer kernels ----------------
__global__ void __launch_bounds__(256) kA(int l, const float* __restrict__ preW,
                                          const float* __restrict__ preb) {
    __shared__ float shW[100 * FD];
    __shared__ float shH[4][FD];
    int tid = threadIdx.x;
    const float* Wp = preW + (size_t)l * 100 * FD;
    for (int i = tid; i < 100 * FD; i += 256) shW[i] = Wp[i];
    int grp = tid >> 6, f = tid & 63;
    int v = blockIdx.x * 4 + grp;
    if (f < FD) shH[grp][f] = g_h[(size_t)v * FD + f];
    __syncthreads();
    if (f < FD) {
        float b = preb[l * FD + f];
        float yv = 0.f;
        #pragma unroll 10
        for (int k = 0; k < FD; k++) {
            float hv = shH[grp][k];
            b  += hv * shW[k * FD + f];
            yv += hv * shW[(FD + k) * FD + f];
        }
        g_base[(size_t)v * FD + f] = b;
        g_y[(size_t)v * FD + f] = yv;
    }
}

__global__ void __launch_bounds__(256) kB() {
    int tid = threadIdx.x;
    int grp = tid >> 6, f = tid & 63;
    int v = blockIdx.x * 4 + grp;
    __nv_bfloat16* eh = g_extH + (size_t)v * KA;
    __nv_bfloat16* el = g_extL + (size_t)v * KA;
    if (f >= FD) {
        int p = 250 + (f - FD);
        if (p < KA) {
            eh[p] = __float2bfloat16(0.f);
            el[p] = __float2bfloat16(0.f);
        }
        return;
    }
    float base = g_base[(size_t)v * FD + f];
    int r0 = g_rowptr[v], r1 = g_rowptr[v + 1];
    float s = 0.f, ss = 0.f, mn = INFINITY, mx = -INFINITY;
    for (int i = r0; i < r1; i++) {
        int u = g_col[i];
        float h = base + g_y[(size_t)u * FD + f];
        s += h; ss += h * h;
        mn = fminf(mn, h); mx = fmaxf(mx, h);
    }
    int deg = r1 - r0;
    float dc = fmaxf((float)deg, 1.f);
    float mean = s / dc;
    float msq = ss / dc;
    float var = fmaxf(msq - mean * mean, 0.f);
    float sd = sqrtf(var + 1e-5f);
    if (deg == 0) { mn = 0.f; mx = 0.f; }
    bsplit(g_h[(size_t)v * FD + f], eh, el, f);
    bsplit(mean, eh, el, 50 + f);
    bsplit(mn,   eh, el, 100 + f);
    bsplit(mx,   eh, el, 150 + f);
    bsplit(sd,   eh, el, 200 + f);
}

__global__ void __launch_bounds__(128) k_zero_bn() {
    int i = threadIdx.x;
    if (i < 128) g_bns[i] = 0.0;
}

// ---------------- mma.sync GEMM + combine epilogue + fused BN stats ----------------
// A: [128 x 256] hi/lo. B: [256 x 192] hi/lo (3 output blocks of 64).
// D = Ah*Bh + Ah*Bl + Al*Bh; final = blk0 + amp*blk1 + att*blk2.
#define SM_A (128 * ASTR)
#define SM_B (NB * ASTR)
#define SMEM_KC ((2 * SM_A + 2 * SM_B) * 2)   // bytes: 51200

__global__ void __launch_bounds__(256) kC_mma(int l) {
    extern __shared__ __nv_bfloat16 dsm[];
    __nv_bfloat16* sAh = dsm;
    __nv_bfloat16* sAl = sAh + SM_A;
    __nv_bfloat16* sBh = sAl + SM_A;
    __nv_bfloat16* sBl = sBh + SM_B;
    __shared__ float redS[64];
    __shared__ float redQ[64];
    int tid = threadIdx.x, lane = tid & 31, wid = tid >> 5;
    int wm = wid & 3, wn = wid >> 2;
    int v0 = blockIdx.x * 128;

    float acc[2][3][4][4] = {};   // [im][blk][jf][quad]

    uint32_t bAh = smem_u32(sAh), bAl = smem_u32(sAl);
    uint32_t bBh = smem_u32(sBh), bBl = smem_u32(sBl);
    int lr = lane & 15, lh = lane >> 4;
    int bgrp = lane >> 3, bli = lane & 7;

    const __nv_bfloat16* BHl = g_CH + (size_t)l * NB * KA;
    const __nv_bfloat16* BLl = g_CL + (size_t)l * NB * KA;

    for (int s = 0; s < KA / 32; s++) {
        int k0 = s * 32;
        __syncthreads();
        // stage A: 128 rows x 32 hi/lo (512 uint4 each, 2/thread)
        #pragma unroll
        for (int t = 0; t < 2; t++) {
            int c = tid + 256 * t;
            int r = c >> 2, q = c & 3;
            int v = v0 + r;
            uint4 h4 = make_uint4(0, 0, 0, 0), l4 = h4;
            if (v < NN) {
                const uint4* ph = (const uint4*)(g_extH + (size_t)v * KA + k0);
                const uint4* pl = (const uint4*)(g_extL + (size_t)v * KA + k0);
                h4 = ph[q]; l4 = pl[q];
            }
            *(uint4*)(sAh + r * ASTR + q * 8) = h4;
            *(uint4*)(sAl + r * ASTR + q * 8) = l4;
        }
        // stage B: 192 rows x 32 hi/lo (768 uint4 each, 3/thread)
        #pragma unroll
        for (int t = 0; t < 3; t++) {
            int c = tid + 256 * t;
            int n2 = c >> 2, q = c & 3;
            const uint4* ph = (const uint4*)(BHl + (size_t)n2 * KA + k0);
            const uint4* pl = (const uint4*)(BLl + (size_t)n2 * KA + k0);
            *(uint4*)(sBh + n2 * ASTR + q * 8) = ph[q];
            *(uint4*)(sBl + n2 * ASTR + q * 8) = pl[q];
        }
        __syncthreads();

        #pragma unroll
        for (int kk = 0; kk < 2; kk++) {
            uint32_t ah[2][4], al[2][4];
            #pragma unroll
            for (int im = 0; im < 2; im++) {
                uint32_t off = (uint32_t)(((wm * 32 + im * 16 + lr) * ASTR + kk * 16 + lh * 8) * 2);
                ldsm4(ah[im], bAh + off);
                ldsm4(al[im], bAl + off);
            }
            #pragma unroll
            for (int blk = 0; blk < 3; blk++) {
                uint32_t bh[4][2], bl[4][2];
                #pragma unroll
                for (int jg = 0; jg < 2; jg++) {
                    uint32_t off = (uint32_t)(((blk * 64 + wn * 32 + jg * 16 + (bgrp >> 1) * 8 + bli) * ASTR
                                               + kk * 16 + (bgrp & 1) * 8) * 2);
                    uint32_t r4[4];
                    ldsm4(r4, bBh + off);
                    bh[jg * 2][0] = r4[0]; bh[jg * 2][1] = r4[1];
                    bh[jg * 2 + 1][0] = r4[2]; bh[jg * 2 + 1][1] = r4[3];
                    ldsm4(r4, bBl + off);
                    bl[jg * 2][0] = r4[0]; bl[jg * 2][1] = r4[1];
                    bl[jg * 2 + 1][0] = r4[2]; bl[jg * 2 + 1][1] = r4[3];
                }
                #pragma unroll
                for (int im = 0; im < 2; im++)
                    #pragma unroll
                    for (int jf = 0; jf < 4; jf++) {
                        mma_bf16(acc[im][blk][jf], ah[im], bh[jf]);
                        mma_bf16(acc[im][blk][jf], ah[im], bl[jf]);
                        mma_bf16(acc[im][blk][jf], al[im], bh[jf]);
                    }
            }
        }
    }

    // epilogue: combine blocks with amp/att, write, fused BN stats
    if (tid < 64) { redS[tid] = 0.f; redQ[tid] = 0.f; }
    __syncthreads();

    float sl[4][2] = {}, ql[4][2] = {};
    int rbase = v0 + wm * 32 + (lane >> 2);
    #pragma unroll
    for (int im = 0; im < 2; im++) {
        int ra = rbase + im * 16;
        int rb = ra + 8;
        bool va = (ra < NN), vb = (rb < NN);
        float ampA = va ? g_amp[ra] : 0.f, attA = va ? g_att[ra] : 0.f;
        float ampB = vb ? g_amp[rb] : 0.f, attB = vb ? g_att[rb] : 0.f;
        #pragma unroll
        for (int jf = 0; jf < 4; jf++) {
            int cb = wn * 32 + jf * 8 + (lane & 3) * 2;
            float f0 = acc[im][0][jf][0] + ampA * acc[im][1][jf][0] + attA * acc[im][2][jf][0];
            float f1 = acc[im][0][jf][1] + ampA * acc[im][1][jf][1] + attA * acc[im][2][jf][1];
            float f2 = acc[im][0][jf][2] + ampB * acc[im][1][jf][2] + attB * acc[im][2][jf][2];
            float f3 = acc[im][0][jf][3] + ampB * acc[im][1][jf][3] + attB * acc[im][2][jf][3];
            if (cb < FD) {
                if (va) *(float2*)&g_h2[(size_t)ra * FD + cb] = make_float2(f0, f1);
                if (vb) *(float2*)&g_h2[(size_t)rb * FD + cb] = make_float2(f2, f3);
            }
            if (va) { sl[jf][0] += f0; ql[jf][0] += f0 * f0; sl[jf][1] += f1; ql[jf][1] += f1 * f1; }
            if (vb) { sl[jf][0] += f2; ql[jf][0] += f2 * f2; sl[jf][1] += f3; ql[jf][1] += f3 * f3; }
        }
    }
    #pragma unroll
    for (int jf = 0; jf < 4; jf++) {
        int cb = wn * 32 + jf * 8 + (lane & 3) * 2;
        atomicAdd(&redS[cb], sl[jf][0]);     atomicAdd(&redQ[cb], ql[jf][0]);
        atomicAdd(&redS[cb + 1], sl[jf][1]); atomicAdd(&redQ[cb + 1], ql[jf][1]);
    }
    __syncthreads();
    if (tid < 64) {
        atomicAdd(&g_bns[tid], (double)redS[tid]);
        atomicAdd(&g_bns[64 + tid], (double)redQ[tid]);
    }
}

__global__ void __launch_bounds__(64) kD(int l, const float* __restrict__ gam,
                                         const float* __restrict__ bet) {
    int f = threadIdx.x;
    if (f < FD) {
        double mu = g_bns[f] / (double)NN;
        double var = g_bns[64 + f] / (double)NN - mu * mu;
        if (var < 0.0) var = 0.0;
        double rs = 1.0 / sqrt(var + 1e-5);
        float sc = (float)rs * gam[l * FD + f];
        g_scale[f] = sc;
        g_shift[f] = bet[l * FD + f] - (float)mu * sc;
    }
}

__global__ void __launch_bounds__(256) kE() {
    int idx = blockIdx.x * 256 + threadIdx.x;
    if (idx < NN * FD) {
        int v = idx / FD;
        int f = idx - v * FD;
        float h = g_h2[idx] * g_scale[f] + g_shift[f];
        g_h[idx] = fmaxf(h, 0.f);
    }
}

// ---------------- readout ----------------
__global__ void __launch_bounds__(256) k_zero_g() {
    int i = blockIdx.x * 256 + threadIdx.x;
    if (i < NG * FD) g_gr[i] = 0.f;
}

__global__ void __launch_bounds__(64) kF(const int* __restrict__ batch) {
    int f = threadIdx.x;
    int v0 = blockIdx.x * 256;
    int vend = min(v0 + 256, NN);
    float acc = 0.f;
    int cur = batch[v0];
    for (int v = v0; v < vend; v++) {
        int b = batch[v];
        if (b != cur) {
            if (f < FD) atomicAdd(&g_gr[cur * FD + f], acc);
            acc = 0.f;
            cur = b;
        }
        if (f < FD) acc += g_h[(size_t)v * FD + f];
    }
    if (f < FD) atomicAdd(&g_gr[cur * FD + f], acc);
}

__global__ void __launch_bounds__(32) kG(const float* __restrict__ W1,
                                         const float* __restrict__ b1,
                                         const float* __restrict__ W2,
                                         const float* __restrict__ b2,
                                         float* __restrict__ out) {
    int gid = blockIdx.x, j = threadIdx.x;
    float p = 0.f;
    if (j < 25) {
        float h = b1[j];
        #pragma unroll 10
        for (int ff = 0; ff < FD; ff++) h += g_gr[gid * FD + ff] * W1[ff * 25 + j];
        h = fmaxf(h, 0.f);
        p = h * W2[j];
    }
    for (int o = 16; o; o >>= 1) p += __shfl_down_sync(0xffffffffu, p, o);
    if (j == 0) out[gid] = p + b2[0];
}

// ---------------- launch ----------------
extern "C" void kernel_launch(void* const* d_in, const int* in_sizes, int n_in,
                              void* d_out, int out_size) {
    const float* x     = (const float*)d_in[0];
    const int*   ei    = (const int*)d_in[1];
    const int*   batch = (const int*)d_in[2];
    const float* Wg    = (const float*)d_in[3];
    const float* bg    = (const float*)d_in[4];
    const float* preW  = (const float*)d_in[5];
    const float* preb  = (const float*)d_in[6];
    const float* postW = (const float*)d_in[7];
    const float* linW  = (const float*)d_in[9];
    const float* gam   = (const float*)d_in[11];
    const float* bet   = (const float*)d_in[12];
    const float* W1    = (const float*)d_in[13];
    const float* b1    = (const float*)d_in[14];
    const float* W2    = (const float*)d_in[15];
    const float* b2    = (const float*)d_in[16];
    float* out = (float*)d_out;

    const int* srcp = ei;
    const int* dstp = ei + NE;

    static int attr_set = 0;
    if (!attr_set) {
        cudaFuncSetAttribute(kC_mma, cudaFuncAttributeMaxDynamicSharedMemorySize, SMEM_KC);
        attr_set = 1;
    }

    k_zero0<<<(NN + 255) / 256, 256>>>();
    k_hist<<<(NE + 255) / 256, 256>>>(dstp);
    k_scan<<<1, SCAN_T>>>();
    k_dinv<<<(NN + 255) / 256, 256>>>();
    k_scatter<<<(NE + 255) / 256, 256>>>(srcp, dstp);
    k_h0s<<<(NN * FD + 255) / 256, 256>>>(x, Wg);
    k_amp<<<(NN + 255) / 256, 256>>>();
    k_gcn<<<NN / 4, 256>>>(bg);
    k_combW<<<(NL * NB * KA + 255) / 256, 256>>>(postW, linW);

    for (int l = 0; l < NL; l++) {
        kA<<<NN / 4, 256>>>(l, preW, preb);
        kB<<<NN / 4, 256>>>();
        k_zero_bn<<<1, 128>>>();
        kC_mma<<<(NN + 127) / 128, 256, SMEM_KC>>>(l);
        kD<<<1, 64>>>(l, gam, bet);
        kE<<<(NN * FD + 255) / 256, 256>>>();
    }

    k_zero_g<<<(NG * FD + 255) / 256, 256>>>();
    kF<<<(NN + 255) / 256, 64>>>(batch);
    kG<<<NG, 32>>>(W1, b1, W2, b2, out);
}

// round 11
// speedup vs baseline: 1.0424x; 1.0424x over previous
#include <cuda_runtime.h>
#include <cuda_bf16.h>
#include <math.h>
#include <stdint.h>

#define NN 100000
#define NE 1600000
#define NG 64
#define FD 50
#define KA 256        // A columns: [h(50) | mean mn mx sd (200) | pad(6)]
#define NB 192        // B columns: 3 blocks of 64
#define NL 3
#define ASTR 40       // smem row stride in bf16 (32 + 8 pad)

// ---------------- static scratch ----------------
__device__ int    g_deg[NN];
__device__ int    g_rowptr[NN + 1];
__device__ int    g_cursor[NN];
__device__ int    g_col[NE];
__device__ float  g_dinv[NN];
__device__ float  g_amp[NN];
__device__ float  g_att[NN];
__device__ double g_avg;
__device__ float  g_h[NN * FD];
__device__ float  g_h2[NN * FD];
__device__ float  g_h0s[NN * FD];
__device__ float  g_base[NN * FD];
__device__ float  g_y[NN * FD];
__device__ __align__(16) __nv_bfloat16 g_extH[(size_t)NN * KA];  // ~51MB
__device__ __align__(16) __nv_bfloat16 g_extL[(size_t)NN * KA];  // ~51MB
__device__ __align__(16) __nv_bfloat16 g_CH[NL * NB * KA];
__device__ __align__(16) __nv_bfloat16 g_CL[NL * NB * KA];
__device__ double g_bns[2 * 64];
__device__ float  g_scale[64];
__device__ float  g_shift[64];
__device__ float  g_gr[NG * FD];

// ---------------- helpers ----------------
__device__ __forceinline__ uint32_t smem_u32(const void* p) {
    uint32_t a;
    asm("{ .reg .u64 t; cvta.to.shared.u64 t, %1; cvt.u32.u64 %0, t; }" : "=r"(a) : "l"(p));
    return a;
}
__device__ __forceinline__ void ldsm4(uint32_t* r, uint32_t a) {
    asm volatile("ldmatrix.sync.aligned.m8n8.x4.shared.b16 {%0,%1,%2,%3}, [%4];"
        : "=r"(r[0]), "=r"(r[1]), "=r"(r[2]), "=r"(r[3]) : "r"(a));
}
__device__ __forceinline__ void mma_bf16(float* d, const uint32_t* a, const uint32_t* b) {
    asm volatile("mma.sync.aligned.m16n8k16.row.col.f32.bf16.bf16.f32 "
        "{%0,%1,%2,%3}, {%4,%5,%6,%7}, {%8,%9}, {%0,%1,%2,%3};"
        : "+f"(d[0]), "+f"(d[1]), "+f"(d[2]), "+f"(d[3])
        : "r"(a[0]), "r"(a[1]), "r"(a[2]), "r"(a[3]), "r"(b[0]), "r"(b[1]));
}
__device__ __forceinline__ void bsplit(float v, __nv_bfloat16* H, __nv_bfloat16* L, size_t i) {
    __nv_bfloat16 h = __float2bfloat16(v);
    H[i] = h;
    L[i] = __float2bfloat16(v - __bfloat162float(h));
}

// ---------------- setup kernels ----------------
__global__ void __launch_bounds__(256) k_zero0() {
    int i = blockIdx.x * 256 + threadIdx.x;
    if (i < NN) g_deg[i] = 0;
    if (i == 0) g_avg = 0.0;
}

__global__ void __launch_bounds__(256) k_hist(const int* __restrict__ dst) {
    int e = blockIdx.x * 256 + threadIdx.x;
    if (e < NE) atomicAdd(&g_deg[dst[e]], 1);
}

#define SCAN_T 1024
#define SCAN_CHUNK 98
__global__ void __launch_bounds__(SCAN_T) k_scan() {
    __shared__ int part[SCAN_T];
    int t = threadIdx.x;
    int st = t * SCAN_CHUNK;
    int s = 0;
    for (int i = 0; i < SCAN_CHUNK; i++) {
        int idx = st + i;
        if (idx < NN) s += g_deg[idx];
    }
    part[t] = s;
    __syncthreads();
    for (int off = 1; off < SCAN_T; off <<= 1) {
        int v = 0;
        if (t >= off) v = part[t - off];
        __syncthreads();
        part[t] += v;
        __syncthreads();
    }
    int run = part[t] - s;
    for (int i = 0; i < SCAN_CHUNK; i++) {
        int idx = st + i;
        if (idx < NN) { g_rowptr[idx] = run; run += g_deg[idx]; }
    }
    if (t == SCAN_T - 1) g_rowptr[NN] = part[SCAN_T - 1];
}

__global__ void __launch_bounds__(256) k_dinv() {
    int v = blockIdx.x * 256 + threadIdx.x;
    float lg = 0.f;
    if (v < NN) {
        int d = g_deg[v];
        g_dinv[v] = rsqrtf((float)(d + 1));
        g_cursor[v] = g_rowptr[v];
        lg = log1pf((float)d);
    }
    for (int o = 16; o; o >>= 1) lg += __shfl_down_sync(0xffffffffu, lg, o);
    __shared__ float ws[8];
    int w = threadIdx.x >> 5, ln = threadIdx.x & 31;
    if (ln == 0) ws[w] = lg;
    __syncthreads();
    if (threadIdx.x == 0) {
        float tt = 0.f;
        for (int i = 0; i < 8; i++) tt += ws[i];
        atomicAdd(&g_avg, (double)tt);
    }
}

__global__ void __launch_bounds__(256) k_scatter(const int* __restrict__ src,
                                                 const int* __restrict__ dst) {
    int e = blockIdx.x * 256 + threadIdx.x;
    if (e < NE) {
        int d = dst[e];
        int p = atomicAdd(&g_cursor[d], 1);
        g_col[p] = src[e];
    }
}

__global__ void __launch_bounds__(256) k_h0s(const float* __restrict__ x,
                                             const float* __restrict__ Wg) {
    int idx = blockIdx.x * 256 + threadIdx.x;
    if (idx < NN * FD) {
        int v = idx / FD;
        int f = idx - v * FD;
        float h0 = x[2 * v] * Wg[f] + x[2 * v + 1] * Wg[FD + f];
        g_h0s[idx] = h0 * g_dinv[v];
    }
}

__global__ void __launch_bounds__(256) k_amp() {
    int v = blockIdx.x * 256 + threadIdx.x;
    if (v < NN) {
        float avgl = (float)(g_avg / (double)NN);
        int d = g_deg[v];
        float dc = fmaxf((float)d, 1.f);
        float lg = log1pf(dc);
        g_amp[v] = lg / avgl;
        g_att[v] = avgl / lg;
    }
}

__global__ void __launch_bounds__(256) k_gcn(const float* __restrict__ bg) {
    int tid = threadIdx.x;
    int grp = tid >> 6, f = tid & 63;
    int v = blockIdx.x * 4 + grp;
    if (f >= FD) return;
    int r0 = g_rowptr[v], r1 = g_rowptr[v + 1];
    float s = 0.f;
    for (int i = r0; i < r1; i++) {
        int u = g_col[i];
        s += g_h0s[(size_t)u * FD + f];
    }
    g_h[(size_t)v * FD + f] = g_dinv[v] * (s + g_h0s[(size_t)v * FD + f]) + bg[f];
}

// ---------------- combined weights (rank-compressed) ----------------
__global__ void __launch_bounds__(256) k_combW(const float* __restrict__ postW,
                                               const float* __restrict__ linW) {
    int idx = blockIdx.x * 256 + threadIdx.x;
    if (idx >= NL * NB * KA) return;
    int l = idx / (NB * KA);
    int r = idx - l * (NB * KA);
    int n2 = r / KA;
    int k = r - n2 * KA;
    int blk = n2 >> 6;
    int n = n2 & 63;
    float v = 0.f;
    int row = -1;
    if (k < FD) { if (blk == 0) row = k; }
    else if (k < 250) row = FD + blk * 200 + (k - FD);
    if (row >= 0 && n < FD) {
        const float* wq = postW + ((size_t)l * 650 + row) * FD;
        const float* wl = linW + (size_t)l * FD * FD;
        #pragma unroll 10
        for (int j = 0; j < FD; j++) v += wq[j] * wl[j * FD + n];
    }
    bsplit(v, g_CH, g_CL, idx);
}

// ---------------- per-layer kernels ----------------
__global__ void __launch_bounds__(256) kA(int l, const float* __restrict__ preW,
                                          const float* __restrict__ preb) {
    __shared__ float shW[100 * FD];
    __shared__ float shH[4][FD];
    int tid = threadIdx.x;
    const float* Wp = preW + (size_t)l * 100 * FD;
    for (int i = tid; i < 100 * FD; i += 256) shW[i] = Wp[i];
    int grp = tid >> 6, f = tid & 63;
    int v = blockIdx.x * 4 + grp;
    if (f < FD) shH[grp][f] = g_h[(size_t)v * FD + f];
    __syncthreads();
    if (f < FD) {
        float b = preb[l * FD + f];
        float yv = 0.f;
        #pragma unroll 10
        for (int k = 0; k < FD; k++) {
            float hv = shH[grp][k];
            b  += hv * shW[k * FD + f];
            yv += hv * shW[(FD + k) * FD + f];
        }
        g_base[(size_t)v * FD + f] = b;
        g_y[(size_t)v * FD + f] = yv;
    }
}

__global__ void __launch_bounds__(256) kB() {
    int tid = threadIdx.x;
    int grp = tid >> 6, f = tid & 63;
    int v = blockIdx.x * 4 + grp;
    __nv_bfloat16* eh = g_extH + (size_t)v * KA;
    __nv_bfloat16* el = g_extL + (size_t)v * KA;
    if (f >= FD) {
        int p = 250 + (f - FD);
        if (p < KA) {
            eh[p] = __float2bfloat16(0.f);
            el[p] = __float2bfloat16(0.f);
        }
        return;
    }
    float base = g_base[(size_t)v * FD + f];
    int r0 = g_rowptr[v], r1 = g_rowptr[v + 1];
    float s = 0.f, ss = 0.f, mn = INFINITY, mx = -INFINITY;
    for (int i = r0; i < r1; i++) {
        int u = g_col[i];
        float h = base + g_y[(size_t)u * FD + f];
        s += h; ss += h * h;
        mn = fminf(mn, h); mx = fmaxf(mx, h);
    }
    int deg = r1 - r0;
    float dc = fmaxf((float)deg, 1.f);
    float mean = s / dc;
    float msq = ss / dc;
    float var = fmaxf(msq - mean * mean, 0.f);
    float sd = sqrtf(var + 1e-5f);
    if (deg == 0) { mn = 0.f; mx = 0.f; }
    bsplit(g_h[(size_t)v * FD + f], eh, el, f);
    bsplit(mean, eh, el, 50 + f);
    bsplit(mn,   eh, el, 100 + f);
    bsplit(mx,   eh, el, 150 + f);
    bsplit(sd,   eh, el, 200 + f);
}

__global__ void __launch_bounds__(128) k_zero_bn() {
    int i = threadIdx.x;
    if (i < 128) g_bns[i] = 0.0;
}

// ---------------- mma.sync GEMM + combine epilogue + fused BN stats ----------------
// 512 threads / 16 warps. Warp tile: 32 rows (wm: 0..3) x 16 cols-per-block (wn: 0..3).
// acc[im2][blk3][jf2][4] = 48 floats/thread.
#define SM_A (128 * ASTR)
#define SM_B (NB * ASTR)
#define SMEM_KC ((2 * SM_A + 2 * SM_B) * 2)   // bytes: 51200

__global__ void __launch_bounds__(512) kC_mma(int l) {
    extern __shared__ __nv_bfloat16 dsm[];
    __nv_bfloat16* sAh = dsm;
    __nv_bfloat16* sAl = sAh + SM_A;
    __nv_bfloat16* sBh = sAl + SM_A;
    __nv_bfloat16* sBl = sBh + SM_B;
    __shared__ float redS[64];
    __shared__ float redQ[64];
    int tid = threadIdx.x, lane = tid & 31, wid = tid >> 5;
    int wm = wid & 3, wn = wid >> 2;      // rows wm*32..+31, cols-within-blk wn*16..+15
    int v0 = blockIdx.x * 128;

    float acc[2][3][2][4] = {};   // [im][blk][jf][quad]

    uint32_t bAh = smem_u32(sAh), bAl = smem_u32(sAl);
    uint32_t bBh = smem_u32(sBh), bBl = smem_u32(sBl);
    int lr = lane & 15, lh = lane >> 4;
    int bgrp = lane >> 3, bli = lane & 7;

    const __nv_bfloat16* BHl = g_CH + (size_t)l * NB * KA;
    const __nv_bfloat16* BLl = g_CL + (size_t)l * NB * KA;

    for (int s = 0; s < KA / 32; s++) {
        int k0 = s * 32;
        __syncthreads();
        // stage A: 128 rows x 32 hi/lo (512 uint4 each; 1/thread)
        {
            int r = tid >> 2, q = tid & 3;
            int v = v0 + r;
            uint4 h4 = make_uint4(0, 0, 0, 0), l4 = h4;
            if (v < NN) {
                const uint4* ph = (const uint4*)(g_extH + (size_t)v * KA + k0);
                const uint4* pl = (const uint4*)(g_extL + (size_t)v * KA + k0);
                h4 = ph[q]; l4 = pl[q];
            }
            *(uint4*)(sAh + r * ASTR + q * 8) = h4;
            *(uint4*)(sAl + r * ASTR + q * 8) = l4;
        }
        // stage B: 192 rows x 32 hi/lo (768 uint4 each; <=2/thread)
        #pragma unroll
        for (int t = 0; t < 2; t++) {
            int c = tid + 512 * t;
            if (c < 768) {
                int n2 = c >> 2, q = c & 3;
                const uint4* ph = (const uint4*)(BHl + (size_t)n2 * KA + k0);
                const uint4* pl = (const uint4*)(BLl + (size_t)n2 * KA + k0);
                *(uint4*)(sBh + n2 * ASTR + q * 8) = ph[q];
                *(uint4*)(sBl + n2 * ASTR + q * 8) = pl[q];
            }
        }
        __syncthreads();

        #pragma unroll
        for (int kk = 0; kk < 2; kk++) {
            uint32_t ah[2][4], al[2][4];
            #pragma unroll
            for (int im = 0; im < 2; im++) {
                uint32_t off = (uint32_t)(((wm * 32 + im * 16 + lr) * ASTR + kk * 16 + lh * 8) * 2);
                ldsm4(ah[im], bAh + off);
                ldsm4(al[im], bAl + off);
            }
            #pragma unroll
            for (int blk = 0; blk < 3; blk++) {
                uint32_t bh[2][2], bl[2][2];
                uint32_t off = (uint32_t)(((blk * 64 + wn * 16 + (bgrp >> 1) * 8 + bli) * ASTR
                                           + kk * 16 + (bgrp & 1) * 8) * 2);
                uint32_t r4[4];
                ldsm4(r4, bBh + off);
                bh[0][0] = r4[0]; bh[0][1] = r4[1];
                bh[1][0] = r4[2]; bh[1][1] = r4[3];
                ldsm4(r4, bBl + off);
                bl[0][0] = r4[0]; bl[0][1] = r4[1];
                bl[1][0] = r4[2]; bl[1][1] = r4[3];
                #pragma unroll
                for (int im = 0; im < 2; im++)
                    #pragma unroll
                    for (int jf = 0; jf < 2; jf++) {
                        mma_bf16(acc[im][blk][jf], ah[im], bh[jf]);
                        mma_bf16(acc[im][blk][jf], ah[im], bl[jf]);
                        mma_bf16(acc[im][blk][jf], al[im], bh[jf]);
                    }
            }
        }
    }

    // epilogue: combine blocks with amp/att, write, fused BN stats
    if (tid < 64) { redS[tid] = 0.f; redQ[tid] = 0.f; }
    __syncthreads();

    float sl[2][2] = {}, ql[2][2] = {};
    int rbase = v0 + wm * 32 + (lane >> 2);
    #pragma unroll
    for (int im = 0; im < 2; im++) {
        int ra = rbase + im * 16;
        int rb = ra + 8;
        bool va = (ra < NN), vb = (rb < NN);
        float ampA = va ? g_amp[ra] : 0.f, attA = va ? g_att[ra] : 0.f;
        float ampB = vb ? g_amp[rb] : 0.f, attB = vb ? g_att[rb] : 0.f;
        #pragma unroll
        for (int jf = 0; jf < 2; jf++) {
            int cb = wn * 16 + jf * 8 + (lane & 3) * 2;
            float f0 = acc[im][0][jf][0] + ampA * acc[im][1][jf][0] + attA * acc[im][2][jf][0];
            float f1 = acc[im][0][jf][1] + ampA * acc[im][1][jf][1] + attA * acc[im][2][jf][1];
            float f2 = acc[im][0][jf][2] + ampB * acc[im][1][jf][2] + attB * acc[im][2][jf][2];
            float f3 = acc[im][0][jf][3] + ampB * acc[im][1][jf][3] + attB * acc[im][2][jf][3];
            if (cb < FD) {
                if (va) *(float2*)&g_h2[(size_t)ra * FD + cb] = make_float2(f0, f1);
                if (vb) *(float2*)&g_h2[(size_t)rb * FD + cb] = make_float2(f2, f3);
            }
            if (va) { sl[jf][0] += f0; ql[jf][0] += f0 * f0; sl[jf][1] += f1; ql[jf][1] += f1 * f1; }
            if (vb) { sl[jf][0] += f2; ql[jf][0] += f2 * f2; sl[jf][1] += f3; ql[jf][1] += f3 * f3; }
        }
    }
    #pragma unroll
    for (int jf = 0; jf < 2; jf++) {
        int cb = wn * 16 + jf * 8 + (lane & 3) * 2;
        atomicAdd(&redS[cb], sl[jf][0]);     atomicAdd(&redQ[cb], ql[jf][0]);
        atomicAdd(&redS[cb + 1], sl[jf][1]); atomicAdd(&redQ[cb + 1], ql[jf][1]);
    }
    __syncthreads();
    if (tid < 64) {
        atomicAdd(&g_bns[tid], (double)redS[tid]);
        atomicAdd(&g_bns[64 + tid], (double)redQ[tid]);
    }
}

__global__ void __launch_bounds__(64) kD(int l, const float* __restrict__ gam,
                                         const float* __restrict__ bet) {
    int f = threadIdx.x;
    if (f < FD) {
        double mu = g_bns[f] / (double)NN;
        double var = g_bns[64 + f] / (double)NN - mu * mu;
        if (var < 0.0) var = 0.0;
        double rs = 1.0 / sqrt(var + 1e-5);
        float sc = (float)rs * gam[l * FD + f];
        g_scale[f] = sc;
        g_shift[f] = bet[l * FD + f] - (float)mu * sc;
    }
}

__global__ void __launch_bounds__(256) kE() {
    int idx = blockIdx.x * 256 + threadIdx.x;
    if (idx < NN * FD) {
        int v = idx / FD;
        int f = idx - v * FD;
        float h = g_h2[idx] * g_scale[f] + g_shift[f];
        g_h[idx] = fmaxf(h, 0.f);
    }
}

// ---------------- readout ----------------
__global__ void __launch_bounds__(256) k_zero_g() {
    int i = blockIdx.x * 256 + threadIdx.x;
    if (i < NG * FD) g_gr[i] = 0.f;
}

__global__ void __launch_bounds__(64) kF(const int* __restrict__ batch) {
    int f = threadIdx.x;
    int v0 = blockIdx.x * 256;
    int vend = min(v0 + 256, NN);
    float acc = 0.f;
    int cur = batch[v0];
    for (int v = v0; v < vend; v++) {
        int b = batch[v];
        if (b != cur) {
            if (f < FD) atomicAdd(&g_gr[cur * FD + f], acc);
            acc = 0.f;
            cur = b;
        }
        if (f < FD) acc += g_h[(size_t)v * FD + f];
    }
    if (f < FD) atomicAdd(&g_gr[cur * FD + f], acc);
}

__global__ void __launch_bounds__(32) kG(const float* __restrict__ W1,
                                         const float* __restrict__ b1,
                                         const float* __restrict__ W2,
                                         const float* __restrict__ b2,
                                         float* __restrict__ out) {
    int gid = blockIdx.x, j = threadIdx.x;
    float p = 0.f;
    if (j < 25) {
        float h = b1[j];
        #pragma unroll 10
        for (int ff = 0; ff < FD; ff++) h += g_gr[gid * FD + ff] * W1[ff * 25 + j];
        h = fmaxf(h, 0.f);
        p = h * W2[j];
    }
    for (int o = 16; o; o >>= 1) p += __shfl_down_sync(0xffffffffu, p, o);
    if (j == 0) out[gid] = p + b2[0];
}

// ---------------- launch ----------------
extern "C" void kernel_launch(void* const* d_in, const int* in_sizes, int n_in,
                              void* d_out, int out_size) {
    const float* x     = (const float*)d_in[0];
    const int*   ei    = (const int*)d_in[1];
    const int*   batch = (const int*)d_in[2];
    const float* Wg    = (const float*)d_in[3];
    const float* bg    = (const float*)d_in[4];
    const float* preW  = (const float*)d_in[5];
    const float* preb  = (const float*)d_in[6];
    const float* postW = (const float*)d_in[7];
    const float* linW  = (const float*)d_in[9];
    const float* gam   = (const float*)d_in[11];
    const float* bet   = (const float*)d_in[12];
    const float* W1    = (const float*)d_in[13];
    const float* b1    = (const float*)d_in[14];
    const float* W2    = (const float*)d_in[15];
    const float* b2    = (const float*)d_in[16];
    float* out = (float*)d_out;

    const int* srcp = ei;
    const int* dstp = ei + NE;

    static int attr_set = 0;
    if (!attr_set) {
        cudaFuncSetAttribute(kC_mma, cudaFuncAttributeMaxDynamicSharedMemorySize, SMEM_KC);
        attr_set = 1;
    }

    k_zero0<<<(NN + 255) / 256, 256>>>();
    k_hist<<<(NE + 255) / 256, 256>>>(dstp);
    k_scan<<<1, SCAN_T>>>();
    k_dinv<<<(NN + 255) / 256, 256>>>();
    k_scatter<<<(NE + 255) / 256, 256>>>(srcp, dstp);
    k_h0s<<<(NN * FD + 255) / 256, 256>>>(x, Wg);
    k_amp<<<(NN + 255) / 256, 256>>>();
    k_gcn<<<NN / 4, 256>>>(bg);
    k_combW<<<(NL * NB * KA + 255) / 256, 256>>>(postW, linW);

    for (int l = 0; l < NL; l++) {
        kA<<<NN / 4, 256>>>(l, preW, preb);
        kB<<<NN / 4, 256>>>();
        k_zero_bn<<<1, 128>>>();
        kC_mma<<<(NN + 127) / 128, 512, SMEM_KC>>>(l);
        kD<<<1, 64>>>(l, gam, bet);
        kE<<<(NN * FD + 255) / 256, 256>>>();
    }

    k_zero_g<<<(NG * FD + 255) / 256, 256>>>();
    kF<<<(NN + 255) / 256, 64>>>(batch);
    kG<<<NG, 32>>>(W1, b1, W2, b2, out);
}